// round 14
// baseline (speedup 1.0000x reference)
#include <cuda_runtime.h>
#include <cuda_fp16.h>
#include <cstdint>

// Problem dims (fixed by the dataset)
#define B_ROWS 65536
#define F_DIM  256
#define U_DIM  1024

// GEMM tiling — R8/R13 proven shape; A now converted fp32->fp16 in-kernel
#define BM 128
#define BN 128
#define BK 64
#define KITERS (F_DIM / BK)       // 4
#define NTHREADS 256

// smem: A 2 stages x 16KB at [0,32K); B 3 stages x 16KB at [32K,80K);
// wsq table 512B at 80K+0; xsq table 512B at 80K+512.
#define A_STG   16384
#define B_OFF   32768
#define B_STG   16384
#define TBL_OFF 81920
#define SMEM_BYTES 82944           // 2 CTAs/SM

// device-global scratch (allocations are forbidden)
__device__ __half g_wt[(size_t)U_DIM * F_DIM];   // w transposed fp16 [U,F]
__device__ float g_wsq_part[8][U_DIM];           // per-f-chunk partial wsq

// ---------------- PTX helpers ----------------
__device__ __forceinline__ uint32_t smem_u32(const void* p) {
    uint32_t a;
    asm("{ .reg .u64 t; cvta.to.shared.u64 t, %1; cvt.u32.u64 %0, t; }" : "=r"(a) : "l"(p));
    return a;
}
__device__ __forceinline__ void cp_async16(uint32_t dst, const void* src) {
    asm volatile("cp.async.cg.shared.global [%0], [%1], 16;" :: "r"(dst), "l"(src));
}
__device__ __forceinline__ void cp_commit() {
    asm volatile("cp.async.commit_group;" ::: "memory");
}
template<int N>
__device__ __forceinline__ void cp_wait() {
    asm volatile("cp.async.wait_group %0;" :: "n"(N) : "memory");
}
__device__ __forceinline__ void ldmatrix_x4(uint32_t* r, uint32_t addr) {
    asm volatile("ldmatrix.sync.aligned.m8n8.x4.shared.b16 {%0,%1,%2,%3}, [%4];"
                 : "=r"(r[0]), "=r"(r[1]), "=r"(r[2]), "=r"(r[3]) : "r"(addr));
}
__device__ __forceinline__ void mma_f16acc(uint32_t* c, const uint32_t* a,
                                           uint32_t b0, uint32_t b1) {
    asm volatile(
        "mma.sync.aligned.m16n8k16.row.col.f16.f16.f16.f16 "
        "{%0,%1}, {%2,%3,%4,%5}, {%6,%7}, {%0,%1};"
        : "+r"(c[0]), "+r"(c[1])
        : "r"(a[0]), "r"(a[1]), "r"(a[2]), "r"(a[3]), "r"(b0), "r"(b1));
}
__device__ __forceinline__ uint32_t pack_h16x2(float lo, float hi) {
    __half2 h = __floats2half2_rn(lo, hi);
    return *reinterpret_cast<uint32_t*>(&h);
}

// ---------------- w-prep: 256 blocks, one wave ----------------
// Block (fo = (bid>>5)*32, uo = (bid&31)*32): 32x32 transpose slice of w,
// fp16 into g_wt, partial column sums of w^2 into g_wsq_part[fo/32].
__global__ void __launch_bounds__(256) wprep_kernel(const float* __restrict__ w) {
    __shared__ float t[32][33];
    __shared__ float red[8][32];
    int tx = threadIdx.x & 31, ty = threadIdx.x >> 5;
    int uo = ((int)blockIdx.x & 31) * 32;
    int fo = ((int)blockIdx.x >> 5) * 32;
    float acc = 0.0f;
    #pragma unroll
    for (int r = 0; r < 4; ++r) {
        int f = ty + 8 * r;
        float v = w[(size_t)(fo + f) * U_DIM + uo + tx];   // coalesced over tx
        t[f][tx] = v;
        acc += v * v;
    }
    __syncthreads();
    #pragma unroll
    for (int r = 0; r < 4; ++r) {
        int u = ty + 8 * r;
        g_wt[(size_t)(uo + u) * F_DIM + fo + tx] = __float2half(t[tx][u]);
    }
    red[ty][tx] = acc;
    __syncthreads();
    if (ty == 0) {
        float s = 0.0f;
        #pragma unroll
        for (int r = 0; r < 8; ++r) s += red[r][tx];
        g_wsq_part[fo >> 5][uo + tx] = s;
    }
}

// ---------------- main GEMM kernel ----------------
// out[m,n] = xsq[m] + wsq[n] - 2 * sum_k x[m,k]*wt[n,k]
// A: x loaded fp32 via LDG, converted to fp16 + STS (2-stage); xsq computed
// from the fp32 values in flight. B: cp.async fp16 3-stage ring (unchanged).
// Single fp16 accumulator bank (K=256). Swizzle identical to prior rounds.
__global__ void __launch_bounds__(NTHREADS, 2) rbf_gemm(float* __restrict__ out,
                                                        const float* __restrict__ x) {
    extern __shared__ char smem[];
    uint32_t sb = smem_u32(smem);

    int tid = threadIdx.x;
    int wid = tid >> 5, lid = tid & 31;
    int g = lid >> 2, t = lid & 3;
    int wm = wid >> 2, wn = wid & 3;          // 2 x 4 warps; warp tile 64x32
    int m0 = blockIdx.y * BM;
    int n0 = blockIdx.x * BN;

    const float*  xa = x    + (size_t)m0 * F_DIM;   // fp32 A source
    const __half* wb = g_wt + (size_t)n0 * F_DIM;

    float* wsq_s = (float*)(smem + TBL_OFF);        // 128 floats
    float* xsq_s = (float*)(smem + TBL_OFF + 512);  // 128 floats

    // wsq table: sum the 8 f-chunk partials for this CTA's n-range
    if (tid < 128) {
        float s = 0.0f;
        #pragma unroll
        for (int p = 0; p < 8; ++p) s += g_wsq_part[p][n0 + tid];
        wsq_s[tid] = s;
    }

    // chunk geometry (shared by A-convert and B-cp.async loaders)
    int crow[4], ccol[4], csoff[4];
    #pragma unroll
    for (int r = 0; r < 4; ++r) {
        int chunk = tid + r * 256;
        crow[r] = chunk >> 3;
        ccol[r] = (chunk & 7) * 8;                       // element col within BK
        csoff[r] = crow[r] * 128 + (((chunk & 7) ^ (crow[r] & 7)) << 4);
    }

    // ldmatrix per-lane bases
    uint32_t rowoffA[4], swzA[4];
    #pragma unroll
    for (int i = 0; i < 4; ++i) {
        int r = wm * 64 + i * 16 + (lid & 15);
        rowoffA[i] = (uint32_t)r * 128;
        swzA[i] = (uint32_t)(r & 7);
    }
    uint32_t rowoffB[2], swzB[2];
    #pragma unroll
    for (int jj = 0; jj < 2; ++jj) {
        int n = wn * 32 + jj * 16 + (lid & 7) + ((lid >> 4) << 3);
        rowoffB[jj] = (uint32_t)n * 128;
        swzB[jj] = (uint32_t)(n & 7);
    }
    uint32_t cA_lane = (uint32_t)(lid >> 4);
    uint32_t cB_lane = (uint32_t)((lid >> 3) & 1);

    float4 av[8];            // A staging regs: 4 chunks x 8 floats
    float xsqp[4] = {0.f, 0.f, 0.f, 0.f};

    auto lda = [&](int kt) {
        #pragma unroll
        for (int r = 0; r < 4; ++r) {
            const float4* p = (const float4*)(xa + (size_t)crow[r] * F_DIM +
                                              kt * BK + ccol[r]);
            av[2 * r] = p[0];
            av[2 * r + 1] = p[1];
        }
    };
    auto sts_a = [&](int stg) {   // convert + store + xsq accumulate
        #pragma unroll
        for (int r = 0; r < 4; ++r) {
            float4 a = av[2 * r], b = av[2 * r + 1];
            xsqp[r] += a.x * a.x + a.y * a.y + a.z * a.z + a.w * a.w
                     + b.x * b.x + b.y * b.y + b.z * b.z + b.w * b.w;
            uint4 pk;
            pk.x = pack_h16x2(a.x, a.y); pk.y = pack_h16x2(a.z, a.w);
            pk.z = pack_h16x2(b.x, b.y); pk.w = pack_h16x2(b.z, b.w);
            *(uint4*)(smem + stg * A_STG + csoff[r]) = pk;
        }
    };
    auto load_B = [&](int kt) {
        uint32_t bbase = sb + B_OFF + (kt % 3) * B_STG;
        #pragma unroll
        for (int r = 0; r < 4; ++r)
            cp_async16(bbase + csoff[r],
                       wb + (size_t)crow[r] * F_DIM + kt * BK + ccol[r]);
    };

    // single fp16 accumulator bank: [i][j][2 regs]
    uint32_t acc[4][4][2];
    #pragma unroll
    for (int i = 0; i < 4; ++i)
        #pragma unroll
        for (int j = 0; j < 4; ++j) { acc[i][j][0] = 0u; acc[i][j][1] = 0u; }

    // prologue: A(0) via regs; B stages 0-2 via cp.async
    lda(0);
    load_B(0); cp_commit();
    load_B(1); cp_commit();
    load_B(2); cp_commit();
    sts_a(0);
    lda(1);

    #pragma unroll
    for (int kt = 0; kt < KITERS; ++kt) {
        cp_wait<2>();          // B(kt) complete
        __syncthreads();       // publishes STS A(kt); WAR for stages

        uint32_t aA = sb + (kt & 1) * A_STG;
        uint32_t aB = sb + B_OFF + (kt % 3) * B_STG;

        #pragma unroll
        for (int ks = 0; ks < 4; ++ks) {
            uint32_t a[4][4], b[2][4];
            uint32_t cA = 2 * ks + cA_lane;
            uint32_t cB = 2 * ks + cB_lane;
            #pragma unroll
            for (int i = 0; i < 4; ++i)
                ldmatrix_x4(a[i], aA + rowoffA[i] + ((cA ^ swzA[i]) << 4));
            #pragma unroll
            for (int jj = 0; jj < 2; ++jj)
                ldmatrix_x4(b[jj], aB + rowoffB[jj] + ((cB ^ swzB[jj]) << 4));
            #pragma unroll
            for (int i = 0; i < 4; ++i)
                #pragma unroll
                for (int jj = 0; jj < 2; ++jj) {
                    mma_f16acc(acc[i][2 * jj + 0], a[i], b[jj][0], b[jj][1]);
                    mma_f16acc(acc[i][2 * jj + 1], a[i], b[jj][2], b[jj][3]);
                }
        }
        __syncthreads();       // all reads of A(kt&1)/B(kt%3) done
        if (kt < KITERS - 1) {
            sts_a((kt + 1) & 1);        // regs A(kt+1) -> smem
            if (kt < KITERS - 2) lda(kt + 2);   // prefetch next A into regs
        }
        if (kt == 0) load_B(3);
        cp_commit();           // one group per kt keeps wait<2> uniform
    }

    // xsq: reduce 8 lanes per row, publish to smem
    #pragma unroll
    for (int r = 0; r < 4; ++r) {
        xsqp[r] += __shfl_xor_sync(0xffffffffu, xsqp[r], 1);
        xsqp[r] += __shfl_xor_sync(0xffffffffu, xsqp[r], 2);
        xsqp[r] += __shfl_xor_sync(0xffffffffu, xsqp[r], 4);
    }
    if ((lid & 7) == 0) {
        #pragma unroll
        for (int r = 0; r < 4; ++r) xsq_s[(tid >> 3) + 32 * r] = xsqp[r];
    }
    __syncthreads();

    // fused epilogue: out = xsq + wsq - 2*cross
    #pragma unroll
    for (int i = 0; i < 4; ++i) {
        int ml = wm * 64 + i * 16 + g;
        float xlo = xsq_s[ml];
        float xhi = xsq_s[ml + 8];
        int mlo = m0 + ml, mhi = mlo + 8;
        #pragma unroll
        for (int j = 0; j < 4; ++j) {
            int nl = wn * 32 + j * 8 + 2 * t;
            float2 ws = *(const float2*)(wsq_s + nl);
            float2 p0 = __half22float2(*(__half2*)&acc[i][j][0]);
            float2 p1 = __half22float2(*(__half2*)&acc[i][j][1]);
            float2 olo, ohi;
            olo.x = fmaf(-2.0f, p0.x, xlo + ws.x);
            olo.y = fmaf(-2.0f, p0.y, xlo + ws.y);
            ohi.x = fmaf(-2.0f, p1.x, xhi + ws.x);
            ohi.y = fmaf(-2.0f, p1.y, xhi + ws.y);
            *(float2*)(out + (size_t)mlo * U_DIM + n0 + nl) = olo;
            *(float2*)(out + (size_t)mhi * U_DIM + n0 + nl) = ohi;
        }
    }
}

// ---------------- host launch ----------------
extern "C" void kernel_launch(void* const* d_in, const int* in_sizes, int n_in,
                              void* d_out, int out_size) {
    const float* x = (const float*)d_in[0];
    const float* w = (const float*)d_in[1];
    float* out = (float*)d_out;

    static int inited = 0;
    if (!inited) {
        cudaFuncSetAttribute(rbf_gemm, cudaFuncAttributeMaxDynamicSharedMemorySize,
                             SMEM_BYTES);
        inited = 1;
    }

    wprep_kernel<<<256, 256>>>(w);

    dim3 grid(U_DIM / BN, B_ROWS / BM);  // (8, 512): n-tiles adjacent -> x reuse in L2
    rbf_gemm<<<grid, NTHREADS, SMEM_BYTES>>>(out, x);
}